// round 2
// baseline (speedup 1.0000x reference)
#include <cuda_runtime.h>

#define T_  3
#define H_  96
#define W_  96
#define C_  128
#define CK  128
#define NHEAD 8
#define DH  16
#define HW_ (H_*W_)
#define NT  (T_*HW_)        // 27648
#define P_  25
#define TP  75
#define KPAD 132            // K/V SMEM row stride (floats)
#define QX  4               // queries per block along x

__device__ float g_Q[NT*CK];
__device__ float g_K[NT*CK];
__device__ float g_V[NT*CK];
__device__ float g_O[NT*CK];

// ---------------------------------------------------------------------------
// fast exp: FFMA-only (magic-number round-to-int + degree-6 2^f poly)
// ---------------------------------------------------------------------------
__device__ __forceinline__ float fexp(float x) {
    float t = fmaxf(x * 1.4426950408889634f, -125.0f);
    float r = t + 12582912.0f;               // round to int (2^23 + 2^22)
    float f = t - (r - 12582912.0f);         // frac in [-0.5, 0.5]
    int  ri = __float_as_int(r) - 0x4B400000;
    float p =              1.5403530393e-4f;
    p = fmaf(p, f, 1.3333558146e-3f);
    p = fmaf(p, f, 9.6181291076e-3f);
    p = fmaf(p, f, 5.5504108665e-2f);
    p = fmaf(p, f, 2.4022650696e-1f);
    p = fmaf(p, f, 6.9314718056e-1f);
    p = fmaf(p, f, 1.0f);
    return p * __int_as_float((ri + 127) << 23);
}

// ---------------------------------------------------------------------------
// Kernel 1: QKV projection + embedding epilogue.
// Block 256 thr = 8 warps. Block tile 64m x 128n. Thread tile 8m x 4n.
// xs stored transposed with odd pad -> conflict-free; A reads are broadcasts.
// ---------------------------------------------------------------------------
__global__ __launch_bounds__(256) void qkv_kernel(
    const float* __restrict__ x,
    const float* __restrict__ Wq,
    const float* __restrict__ Wk,
    const float* __restrict__ Wv,
    const float* __restrict__ temp_emb,
    const float* __restrict__ sp_emb)
{
    __shared__ float xs_t[32][65];   // [k][m], odd pad
    __shared__ float ws[32][128];    // [k][n]

    const int which = blockIdx.y;
    const float* Wm = (which == 0) ? Wq : (which == 1) ? Wk : Wv;
    float* dst      = (which == 0) ? g_Q : (which == 1) ? g_K : g_V;

    const int m0  = blockIdx.x * 64;
    const int tid = threadIdx.x;
    const int tx  = tid & 31;        // n-group (4 floats)
    const int ty  = tid >> 5;        // m-group (8 rows)

    float acc[8][4];
#pragma unroll
    for (int i = 0; i < 8; i++)
#pragma unroll
        for (int j = 0; j < 4; j++) acc[i][j] = 0.f;

    for (int k0 = 0; k0 < 128; k0 += 32) {
        // x tile 64x32 -> transposed SMEM
        {
            int idx = tid;
#pragma unroll
            for (int it = 0; it < 2; it++) {
                int m = idx >> 3, k4 = idx & 7;
                float4 v = *(const float4*)&x[(size_t)(m0 + m) * 128 + k0 + k4 * 4];
                xs_t[k4 * 4 + 0][m] = v.x;
                xs_t[k4 * 4 + 1][m] = v.y;
                xs_t[k4 * 4 + 2][m] = v.z;
                xs_t[k4 * 4 + 3][m] = v.w;
                idx += 256;
            }
        }
        // w tile 32x128
        {
            int idx = tid;
#pragma unroll
            for (int it = 0; it < 4; it++) {
                int k = idx >> 5, c4 = idx & 31;
                *(float4*)&ws[k][c4 * 4] =
                    *(const float4*)&Wm[(size_t)(k0 + k) * 128 + c4 * 4];
                idx += 256;
            }
        }
        __syncthreads();
#pragma unroll
        for (int kk = 0; kk < 32; kk++) {
            float b0_[4];
            float4 bv = *(float4*)&ws[kk][tx * 4];
            b0_[0] = bv.x; b0_[1] = bv.y; b0_[2] = bv.z; b0_[3] = bv.w;
#pragma unroll
            for (int i = 0; i < 8; i++) {
                float a = xs_t[kk][ty * 8 + i];
#pragma unroll
                for (int j = 0; j < 4; j++) acc[i][j] = fmaf(a, b0_[j], acc[i][j]);
            }
        }
        __syncthreads();
    }

#pragma unroll
    for (int i = 0; i < 8; i++) {
        const int n    = m0 + ty * 8 + i;
        const int t    = n / HW_;
        const int rem  = n % HW_;
        const int yq   = rem / W_;
        const int xq   = rem % W_;
        const int col0 = tx * 4;

        if (which <= 1) {
#pragma unroll
            for (int j = 0; j < 4; j++) acc[i][j] += temp_emb[t * CK + col0 + j];
        }
        if (which == 0) {
            const int yc = min(max(yq, 2), H_ - 3);
            const int xc = min(max(xq, 2), W_ - 3);
            const int qidx = (yq - yc + 2) * 5 + (xq - xc + 2);
#pragma unroll
            for (int j = 0; j < 4; j++) acc[i][j] += sp_emb[qidx * CK + col0 + j];
        }
        *(float4*)&dst[(size_t)n * CK + col0] =
            make_float4(acc[i][0], acc[i][1], acc[i][2], acc[i][3]);
    }
}

// ---------------------------------------------------------------------------
// Kernel 2: attention, tiled 4 queries along x per block.
// Block = (y, x0..x0+3). 768 thr = 24 warps = (t_query, head).
// K region: 3 frames x 5 y x 8 x = 120 rows, loaded once, shared by 4 queries.
// sp_emb contribution separated: score = (Q.K + Q.sp[p]) * scale.
// ---------------------------------------------------------------------------
__global__ __launch_bounds__(768) void attn_kernel(const float* __restrict__ sp_emb)
{
    extern __shared__ float sm[];
    float* Ksm  = sm;                       // 120 x KPAD
    float* Vsm  = Ksm + 120 * KPAD;         // 120 x KPAD
    float* Qsm  = Vsm + 120 * KPAD;         // 12 x 128  [(qx*3+t)][c]
    float* SPs  = Qsm + 12 * 128;           // 25 x 128
    float* Asm  = SPs + 25 * 128;           // 24 x 76
    int*   rowm = (int*)(Asm + 24 * 76);    // 75 (+pad)

    const int y   = blockIdx.y;
    const int x0  = blockIdx.x * QX;
    const int tid = threadIdx.x;

    const int ybase = min(max(y, 2), H_ - 3) - 2;
    const int xbase = min(max(x0, 2), W_ - 3) - 2;

    if (tid < TP) {
        int tk = tid / 25, p = tid % 25;
        rowm[tid] = (tk * 5 + p / 5) * 8 + (p % 5);
    }
    // Q rows (12 x 128)
    for (int i = tid; i < 12 * 128; i += 768) {
        int row = i >> 7, c = i & 127;
        int qx = row / 3, t = row % 3;
        Qsm[i] = g_Q[(size_t)(t * HW_ + y * W_ + x0 + qx) * CK + c];
    }
    // sp_emb copy
    for (int i = tid; i < 25 * 128; i += 768) SPs[i] = sp_emb[i];
    // K/V gather: 120 rows x 32 float4
    for (int i = tid; i < 120 * 32; i += 768) {
        int row = i >> 5, c4 = (i & 31) * 4;
        int t  = row / 40, rem = row % 40;
        int ky = rem >> 3, kx = rem & 7;
        int col = min(xbase + kx, W_ - 1);
        size_t n = (size_t)(t * HW_ + (ybase + ky) * W_ + col) * CK + c4;
        *(float4*)&Ksm[row * KPAD + c4] = *(const float4*)&g_K[n];
        *(float4*)&Vsm[row * KPAD + c4] = *(const float4*)&g_V[n];
    }
    __syncthreads();

    const int w    = tid >> 5;
    const int lane = tid & 31;
    const int tq   = w / NHEAD;
    const int h    = w % NHEAD;
    const int hoff = h * DH;

#pragma unroll 1
    for (int qx = 0; qx < QX; qx++) {
        const int xc   = min(max(x0 + qx, 2), W_ - 3);
        const int xoff = (xc - 2) - xbase;     // 0..3

        float4 q0 = *(float4*)&Qsm[(qx * 3 + tq) * 128 + hoff];
        float4 q1 = *(float4*)&Qsm[(qx * 3 + tq) * 128 + hoff + 4];
        float4 q2 = *(float4*)&Qsm[(qx * 3 + tq) * 128 + hoff + 8];
        float4 q3 = *(float4*)&Qsm[(qx * 3 + tq) * 128 + hoff + 12];

        // per-lane Q . sp_emb[p] (lanes 0..24)
        float qsp = 0.f;
        if (lane < 25) {
            const float* sp = &SPs[lane * 128 + hoff];
            float4 s0 = *(const float4*)&sp[0];
            float4 s1 = *(const float4*)&sp[4];
            float4 s2 = *(const float4*)&sp[8];
            float4 s3 = *(const float4*)&sp[12];
            qsp = q0.x*s0.x + q0.y*s0.y + q0.z*s0.z + q0.w*s0.w
                + q1.x*s1.x + q1.y*s1.y + q1.z*s1.z + q1.w*s1.w
                + q2.x*s2.x + q2.y*s2.y + q2.z*s2.z + q2.w*s2.w
                + q3.x*s3.x + q3.y*s3.y + q3.z*s3.z + q3.w*s3.w;
        }

        float sc[3];
        float mloc = -1e30f;
#pragma unroll
        for (int r = 0; r < 3; r++) {
            int j  = lane + 32 * r;
            int tk = (j >= 50) ? 2 : ((j >= 25) ? 1 : 0);
            int p  = min(j - tk * 25, 24);
            float qspp = __shfl_sync(0xffffffffu, qsp, p);   // full-warp shfl
            float s = -1e30f;
            if (j < TP) {
                const float* kr = &Ksm[(rowm[j] + xoff) * KPAD + hoff];
                float4 k0 = *(const float4*)&kr[0];
                float4 k1 = *(const float4*)&kr[4];
                float4 k2 = *(const float4*)&kr[8];
                float4 k3 = *(const float4*)&kr[12];
                float dk = q0.x*k0.x + q0.y*k0.y + q0.z*k0.z + q0.w*k0.w
                         + q1.x*k1.x + q1.y*k1.y + q1.z*k1.z + q1.w*k1.w
                         + q2.x*k2.x + q2.y*k2.y + q2.z*k2.z + q2.w*k2.w
                         + q3.x*k3.x + q3.y*k3.y + q3.z*k3.z + q3.w*k3.w;
                s = (dk + qspp) * 0.25f;
            }
            sc[r] = s;
            mloc = fmaxf(mloc, s);
        }
#pragma unroll
        for (int o = 16; o; o >>= 1)
            mloc = fmaxf(mloc, __shfl_xor_sync(0xffffffffu, mloc, o));

        float ssum = 0.f;
#pragma unroll
        for (int r = 0; r < 3; r++) {
            int j = lane + 32 * r;
            if (j < TP) {
                float e = fexp(sc[r] - mloc);
                ssum += e;
                Asm[w * 76 + j] = e;
            }
        }
#pragma unroll
        for (int o = 16; o; o >>= 1)
            ssum += __shfl_xor_sync(0xffffffffu, ssum, o);
        float rs = __fdividef(1.f, ssum);
        __syncwarp();

        // AV: lanes = (d 0..15, half); halves interleave keys
        const int d  = lane & 15;
        const int hf = lane >> 4;
        float acc = 0.f;
        for (int j = hf; j < TP; j += 2)
            acc += Asm[w * 76 + j] * Vsm[(rowm[j] + xoff) * KPAD + hoff + d];
        acc += __shfl_xor_sync(0xffffffffu, acc, 16);

        if (hf == 0) {
            g_O[(size_t)(tq * HW_ + y * W_ + x0 + qx) * CK + hoff + d] = acc * rs;
        }
        __syncwarp();
    }
}

// ---------------------------------------------------------------------------
// Kernel 3: output projection O @ Wo, transposed writeout.
// Same tiling as qkv_kernel.
// ---------------------------------------------------------------------------
__global__ __launch_bounds__(256) void outproj_kernel(
    const float* __restrict__ Wo, float* __restrict__ out)
{
    __shared__ float xs_t[32][65];
    __shared__ float ws[32][128];

    const int m0  = blockIdx.x * 64;
    const int tid = threadIdx.x;
    const int tx  = tid & 31;
    const int ty  = tid >> 5;

    float acc[8][4];
#pragma unroll
    for (int i = 0; i < 8; i++)
#pragma unroll
        for (int j = 0; j < 4; j++) acc[i][j] = 0.f;

    for (int k0 = 0; k0 < 128; k0 += 32) {
        {
            int idx = tid;
#pragma unroll
            for (int it = 0; it < 2; it++) {
                int m = idx >> 3, k4 = idx & 7;
                float4 v = *(const float4*)&g_O[(size_t)(m0 + m) * 128 + k0 + k4 * 4];
                xs_t[k4 * 4 + 0][m] = v.x;
                xs_t[k4 * 4 + 1][m] = v.y;
                xs_t[k4 * 4 + 2][m] = v.z;
                xs_t[k4 * 4 + 3][m] = v.w;
                idx += 256;
            }
        }
        {
            int idx = tid;
#pragma unroll
            for (int it = 0; it < 4; it++) {
                int k = idx >> 5, c4 = idx & 31;
                *(float4*)&ws[k][c4 * 4] =
                    *(const float4*)&Wo[(size_t)(k0 + k) * 128 + c4 * 4];
                idx += 256;
            }
        }
        __syncthreads();
#pragma unroll
        for (int kk = 0; kk < 32; kk++) {
            float b0_[4];
            float4 bv = *(float4*)&ws[kk][tx * 4];
            b0_[0] = bv.x; b0_[1] = bv.y; b0_[2] = bv.z; b0_[3] = bv.w;
#pragma unroll
            for (int i = 0; i < 8; i++) {
                float a = xs_t[kk][ty * 8 + i];
#pragma unroll
                for (int j = 0; j < 4; j++) acc[i][j] = fmaf(a, b0_[j], acc[i][j]);
            }
        }
        __syncthreads();
    }

#pragma unroll
    for (int i = 0; i < 8; i++) {
        const int n    = m0 + ty * 8 + i;
        const int t    = n / HW_;
        const int rem  = n % HW_;
        const int col0 = tx * 4;
        const size_t o = (size_t)rem * (T_ * C_) + t * C_ + col0;
        *(float4*)&out[o] = make_float4(acc[i][0], acc[i][1], acc[i][2], acc[i][3]);
    }
}

// ---------------------------------------------------------------------------
extern "C" void kernel_launch(void* const* d_in, const int* in_sizes, int n_in,
                              void* d_out, int out_size)
{
    const float* x    = (const float*)d_in[0];
    const float* Wq   = (const float*)d_in[1];
    const float* Wk   = (const float*)d_in[2];
    const float* Wv   = (const float*)d_in[3];
    const float* Wo   = (const float*)d_in[4];
    const float* temp = (const float*)d_in[5];
    const float* sp   = (const float*)d_in[6];
    float* out = (float*)d_out;

    qkv_kernel<<<dim3(NT / 64, 3), 256>>>(x, Wq, Wk, Wv, temp, sp);

    const size_t smem = (size_t)(2 * 120 * KPAD + 12 * 128 + 25 * 128 + 24 * 76) * sizeof(float)
                      + 80 * sizeof(int);
    cudaFuncSetAttribute(attn_kernel, cudaFuncAttributeMaxDynamicSharedMemorySize, (int)smem);
    attn_kernel<<<dim3(W_ / QX, H_), 768, smem>>>(sp);

    outproj_kernel<<<NT / 64, 256>>>(Wo, out);
}

// round 3
// speedup vs baseline: 1.6561x; 1.6561x over previous
#include <cuda_runtime.h>

#define T_  3
#define H_  96
#define W_  96
#define C_  128
#define CK  128
#define NHEAD 8
#define DH  16
#define HW_ (H_*W_)
#define NT  (T_*HW_)        // 27648
#define QX  4
#define KPAD 132            // fp32 row stride (16B aligned, conflict-spread)

typedef unsigned long long u64;

__device__ float g_Q[NT*CK];
__device__ float g_K[NT*CK];
__device__ float g_V[NT*CK];
__device__ float g_O[NT*CK];

// ---------------- f32x2 helpers ----------------
__device__ __forceinline__ u64 ffma2(u64 a, u64 b, u64 c) {
    u64 d; asm("fma.rn.f32x2 %0,%1,%2,%3;" : "=l"(d) : "l"(a), "l"(b), "l"(c)); return d;
}
__device__ __forceinline__ u64 fadd2(u64 a, u64 b) {
    u64 d; asm("add.rn.f32x2 %0,%1,%2;" : "=l"(d) : "l"(a), "l"(b)); return d;
}
__device__ __forceinline__ u64 pack2(float lo, float hi) {
    u64 d; asm("mov.b64 %0,{%1,%2};" : "=l"(d) : "f"(lo), "f"(hi)); return d;
}
__device__ __forceinline__ float2 unpack2(u64 v) {
    float2 r; asm("mov.b64 {%0,%1},%2;" : "=f"(r.x), "=f"(r.y) : "l"(v)); return r;
}

__device__ __forceinline__ float fexp(float x) {
    float t = fmaxf(x * 1.4426950408889634f, -125.0f);
    float r = t + 12582912.0f;
    float f = t - (r - 12582912.0f);
    int  ri = __float_as_int(r) - 0x4B400000;
    float p =              1.5403530393e-4f;
    p = fmaf(p, f, 1.3333558146e-3f);
    p = fmaf(p, f, 9.6181291076e-3f);
    p = fmaf(p, f, 5.5504108665e-2f);
    p = fmaf(p, f, 2.4022650696e-1f);
    p = fmaf(p, f, 6.9314718056e-1f);
    p = fmaf(p, f, 1.0f);
    return p * __int_as_float((ri + 127) << 23);
}

// ---------------------------------------------------------------------------
// Kernel 1: QKV projection + embedding epilogue. f32x2 inner loop.
// Block 256 thr, tile 64m x 128n, thread tile 8m x 4n (m paired as f32x2).
// ---------------------------------------------------------------------------
__global__ __launch_bounds__(256) void qkv_kernel(
    const float* __restrict__ x,
    const float* __restrict__ Wq,
    const float* __restrict__ Wk,
    const float* __restrict__ Wv,
    const float* __restrict__ temp_emb,
    const float* __restrict__ sp_emb)
{
    __shared__ float xs_t[32][68];   // [k][m], 16B-aligned stride
    __shared__ float ws[32][128];    // [k][n]

    const int which = blockIdx.y;
    const float* Wm = (which == 0) ? Wq : (which == 1) ? Wk : Wv;
    float* dst      = (which == 0) ? g_Q : (which == 1) ? g_K : g_V;

    const int m0  = blockIdx.x * 64;
    const int tid = threadIdx.x;
    const int tx  = tid & 31;
    const int ty  = tid >> 5;

    u64 acc[4][4];   // [m-pair][n]
#pragma unroll
    for (int p = 0; p < 4; p++)
#pragma unroll
        for (int j = 0; j < 4; j++) acc[p][j] = 0ull;

    for (int k0 = 0; k0 < 128; k0 += 32) {
        {
            int idx = tid;
#pragma unroll
            for (int it = 0; it < 2; it++) {
                int m = idx >> 3, k4 = idx & 7;
                float4 v = *(const float4*)&x[(size_t)(m0 + m) * 128 + k0 + k4 * 4];
                xs_t[k4 * 4 + 0][m] = v.x;
                xs_t[k4 * 4 + 1][m] = v.y;
                xs_t[k4 * 4 + 2][m] = v.z;
                xs_t[k4 * 4 + 3][m] = v.w;
                idx += 256;
            }
        }
        {
            int idx = tid;
#pragma unroll
            for (int it = 0; it < 4; it++) {
                int k = idx >> 5, c4 = idx & 31;
                *(float4*)&ws[k][c4 * 4] =
                    *(const float4*)&Wm[(size_t)(k0 + k) * 128 + c4 * 4];
                idx += 256;
            }
        }
        __syncthreads();
#pragma unroll
        for (int kk = 0; kk < 32; kk++) {
            float4 bv = *(const float4*)&ws[kk][tx * 4];
            u64 b0 = pack2(bv.x, bv.x), b1 = pack2(bv.y, bv.y);
            u64 b2 = pack2(bv.z, bv.z), b3 = pack2(bv.w, bv.w);
            ulonglong2 a01 = *(const ulonglong2*)&xs_t[kk][ty * 8];
            ulonglong2 a23 = *(const ulonglong2*)&xs_t[kk][ty * 8 + 4];
            acc[0][0] = ffma2(a01.x, b0, acc[0][0]);
            acc[0][1] = ffma2(a01.x, b1, acc[0][1]);
            acc[0][2] = ffma2(a01.x, b2, acc[0][2]);
            acc[0][3] = ffma2(a01.x, b3, acc[0][3]);
            acc[1][0] = ffma2(a01.y, b0, acc[1][0]);
            acc[1][1] = ffma2(a01.y, b1, acc[1][1]);
            acc[1][2] = ffma2(a01.y, b2, acc[1][2]);
            acc[1][3] = ffma2(a01.y, b3, acc[1][3]);
            acc[2][0] = ffma2(a23.x, b0, acc[2][0]);
            acc[2][1] = ffma2(a23.x, b1, acc[2][1]);
            acc[2][2] = ffma2(a23.x, b2, acc[2][2]);
            acc[2][3] = ffma2(a23.x, b3, acc[2][3]);
            acc[3][0] = ffma2(a23.y, b0, acc[3][0]);
            acc[3][1] = ffma2(a23.y, b1, acc[3][1]);
            acc[3][2] = ffma2(a23.y, b2, acc[3][2]);
            acc[3][3] = ffma2(a23.y, b3, acc[3][3]);
        }
        __syncthreads();
    }

    const int col0 = tx * 4;
#pragma unroll
    for (int p = 0; p < 4; p++) {
        float2 c0 = unpack2(acc[p][0]);
        float2 c1 = unpack2(acc[p][1]);
        float2 c2 = unpack2(acc[p][2]);
        float2 c3 = unpack2(acc[p][3]);
        float rowv[2][4] = {{c0.x, c1.x, c2.x, c3.x}, {c0.y, c1.y, c2.y, c3.y}};
#pragma unroll
        for (int rr = 0; rr < 2; rr++) {
            const int n   = m0 + ty * 8 + 2 * p + rr;
            const int t   = n / HW_;
            const int rem = n % HW_;
            if (which <= 1) {
#pragma unroll
                for (int j = 0; j < 4; j++) rowv[rr][j] += temp_emb[t * CK + col0 + j];
            }
            if (which == 0) {
                const int yq = rem / W_;
                const int xq = rem % W_;
                const int yc = min(max(yq, 2), H_ - 3);
                const int xc = min(max(xq, 2), W_ - 3);
                const int qidx = (yq - yc + 2) * 5 + (xq - xc + 2);
#pragma unroll
                for (int j = 0; j < 4; j++) rowv[rr][j] += sp_emb[qidx * CK + col0 + j];
            }
            *(float4*)&dst[(size_t)n * CK + col0] =
                make_float4(rowv[rr][0], rowv[rr][1], rowv[rr][2], rowv[rr][3]);
        }
    }
}

// ---------------------------------------------------------------------------
// Kernel 2: attention. Block = (y, 4 queries along x). 768 thr = 24 warps
// = (t_query, head). Scores in registers, one __syncthreads total.
// ---------------------------------------------------------------------------
__global__ __launch_bounds__(768) void attn_kernel(const float* __restrict__ sp_emb)
{
    extern __shared__ float sm[];
    float* Ksm = sm;                    // 120 x KPAD
    float* Vsm = Ksm + 120 * KPAD;      // 120 x KPAD
    float* Qsm = Vsm + 120 * KPAD;      // 12 x KPAD  row = qx*3 + t
    float* SPs = Qsm + 12 * KPAD;       // 25 x KPAD

    const int y   = blockIdx.y;
    const int x0  = blockIdx.x * QX;
    const int tid = threadIdx.x;

    const int ybase = min(max(y, 2), H_ - 3) - 2;
    const int xbase = min(max(x0, 2), W_ - 3) - 2;

    // gather K, V (rows: t*40 + ky*8 + kx)
#pragma unroll
    for (int it = 0; it < 5; it++) {
        int i = tid + it * 768;
        int row = i >> 5, c4 = (i & 31) * 4;
        int t = row / 40, rem = row % 40;
        int ky = rem >> 3, kx = rem & 7;
        int col = min(xbase + kx, W_ - 1);
        size_t g = (size_t)(t * HW_ + (ybase + ky) * W_ + col) * CK + c4;
        *(float4*)&Ksm[row * KPAD + c4] = *(const float4*)&g_K[g];
        *(float4*)&Vsm[row * KPAD + c4] = *(const float4*)&g_V[g];
    }
    // Q (12 rows)
#pragma unroll
    for (int it = 0; it < 2; it++) {
        int i = tid + it * 768;
        int row = i >> 7, c = i & 127;
        int qx = row / 3, t = row % 3;
        Qsm[row * KPAD + c] = g_Q[(size_t)(t * HW_ + y * W_ + x0 + qx) * CK + c];
    }
    // sp_emb (25 rows)
    for (int i = tid; i < 25 * 128; i += 768) {
        int p = i >> 7, c = i & 127;
        SPs[p * KPAD + c] = sp_emb[i];
    }
    __syncthreads();

    const int lane = tid & 31;
    const int w    = tid >> 5;
    const int tq   = w / NHEAD;
    const int h    = w % NHEAD;
    const int hoff = h * DH;

    // ---- phase 1: scores (lane = qx*8 + rl) ----
    const int qx  = lane >> 3;
    const int rl  = lane & 7;
    const int xoffq = min(max(x0 + qx, 2), W_ - 3) - 2 - xbase;   // 0..3
    const int kxr   = rl - xoffq;
    const bool valid = (kxr >= 0) && (kxr <= 4);
    const int kxrc  = min(max(kxr, 0), 4);

    const float* qp = &Qsm[(qx * 3 + tq) * KPAD + hoff];
    ulonglong2 qA = *(const ulonglong2*)&qp[0];
    ulonglong2 qB = *(const ulonglong2*)&qp[4];
    ulonglong2 qC = *(const ulonglong2*)&qp[8];
    ulonglong2 qD = *(const ulonglong2*)&qp[12];

    float a[15];
#pragma unroll
    for (int tk = 0; tk < 3; tk++) {
#pragma unroll
        for (int i5 = 0; i5 < 5; i5++) {
            const float* kr = &Ksm[(tk * 40 + i5 * 8 + rl) * KPAD + hoff];
            ulonglong2 k0 = *(const ulonglong2*)&kr[0];
            ulonglong2 k1 = *(const ulonglong2*)&kr[4];
            ulonglong2 k2 = *(const ulonglong2*)&kr[8];
            ulonglong2 k3 = *(const ulonglong2*)&kr[12];
            u64 s = ffma2(qA.x, k0.x, 0ull);
            s = ffma2(qA.y, k0.y, s);
            s = ffma2(qB.x, k1.x, s);
            s = ffma2(qB.y, k1.y, s);
            s = ffma2(qC.x, k2.x, s);
            s = ffma2(qC.y, k2.y, s);
            s = ffma2(qD.x, k3.x, s);
            s = ffma2(qD.y, k3.y, s);
            float2 f = unpack2(s);
            a[tk * 5 + i5] = f.x + f.y;
        }
    }

    // per-lane Q . sp_emb[p] for p = i5*5 + kxrc
    float qsp[5];
#pragma unroll
    for (int i5 = 0; i5 < 5; i5++) {
        const float* sp = &SPs[(i5 * 5 + kxrc) * KPAD + hoff];
        ulonglong2 s0 = *(const ulonglong2*)&sp[0];
        ulonglong2 s1 = *(const ulonglong2*)&sp[4];
        ulonglong2 s2 = *(const ulonglong2*)&sp[8];
        ulonglong2 s3 = *(const ulonglong2*)&sp[12];
        u64 s = ffma2(qA.x, s0.x, 0ull);
        s = ffma2(qA.y, s0.y, s);
        s = ffma2(qB.x, s1.x, s);
        s = ffma2(qB.y, s1.y, s);
        s = ffma2(qC.x, s2.x, s);
        s = ffma2(qC.y, s2.y, s);
        s = ffma2(qD.x, s3.x, s);
        s = ffma2(qD.y, s3.y, s);
        float2 f = unpack2(s);
        qsp[i5] = f.x + f.y;
    }

    // exp + sum (scores are O(1): no max subtraction needed)
    float ssum = 0.f;
#pragma unroll
    for (int tk = 0; tk < 3; tk++)
#pragma unroll
        for (int i5 = 0; i5 < 5; i5++) {
            int idx = tk * 5 + i5;
            float s = (a[idx] + qsp[i5]) * 0.25f;
            float e = valid ? fexp(s) : 0.f;
            a[idx] = e;
            ssum += e;
        }
    ssum += __shfl_xor_sync(0xffffffffu, ssum, 1);
    ssum += __shfl_xor_sync(0xffffffffu, ssum, 2);
    ssum += __shfl_xor_sync(0xffffffffu, ssum, 4);
    float rs = __fdividef(1.f, ssum);

    // ---- phase 2: AV (lane = d4*8 + rl, same rl -> same rows as phase 1) ----
    const int d4 = lane >> 3;
    u64 acc[4][2];
#pragma unroll
    for (int q = 0; q < 4; q++) { acc[q][0] = 0ull; acc[q][1] = 0ull; }

#pragma unroll
    for (int tk = 0; tk < 3; tk++) {
#pragma unroll
        for (int i5 = 0; i5 < 5; i5++) {
            const int idx = tk * 5 + i5;
            const float* vr = &Vsm[(tk * 40 + i5 * 8 + rl) * KPAD + hoff + d4 * 4];
            ulonglong2 v = *(const ulonglong2*)vr;
#pragma unroll
            for (int q = 0; q < 4; q++) {
                float av = __shfl_sync(0xffffffffu, a[idx], (q << 3) | rl);
                u64 aa = pack2(av, av);
                acc[q][0] = ffma2(aa, v.x, acc[q][0]);
                acc[q][1] = ffma2(aa, v.y, acc[q][1]);
            }
        }
    }
    // reduce over the 8 rl lanes
#pragma unroll
    for (int off = 1; off <= 4; off <<= 1) {
#pragma unroll
        for (int q = 0; q < 4; q++) {
            acc[q][0] = fadd2(acc[q][0], __shfl_xor_sync(0xffffffffu, acc[q][0], off));
            acc[q][1] = fadd2(acc[q][1], __shfl_xor_sync(0xffffffffu, acc[q][1], off));
        }
    }
    float rsw = __shfl_sync(0xffffffffu, rs, (lane & 7) * 8);
    if (rl < 4) {
        float2 lo = unpack2(acc[rl][0]);
        float2 hi = unpack2(acc[rl][1]);
        float4 o = make_float4(lo.x * rsw, lo.y * rsw, hi.x * rsw, hi.y * rsw);
        *(float4*)&g_O[(size_t)(tq * HW_ + y * W_ + x0 + rl) * CK + hoff + d4 * 4] = o;
    }
}

// ---------------------------------------------------------------------------
// Kernel 3: output projection O @ Wo, transposed writeout. f32x2 inner loop.
// ---------------------------------------------------------------------------
__global__ __launch_bounds__(256) void outproj_kernel(
    const float* __restrict__ Wo, float* __restrict__ out)
{
    __shared__ float xs_t[32][68];
    __shared__ float ws[32][128];

    const int m0  = blockIdx.x * 64;
    const int tid = threadIdx.x;
    const int tx  = tid & 31;
    const int ty  = tid >> 5;

    u64 acc[4][4];
#pragma unroll
    for (int p = 0; p < 4; p++)
#pragma unroll
        for (int j = 0; j < 4; j++) acc[p][j] = 0ull;

    for (int k0 = 0; k0 < 128; k0 += 32) {
        {
            int idx = tid;
#pragma unroll
            for (int it = 0; it < 2; it++) {
                int m = idx >> 3, k4 = idx & 7;
                float4 v = *(const float4*)&g_O[(size_t)(m0 + m) * 128 + k0 + k4 * 4];
                xs_t[k4 * 4 + 0][m] = v.x;
                xs_t[k4 * 4 + 1][m] = v.y;
                xs_t[k4 * 4 + 2][m] = v.z;
                xs_t[k4 * 4 + 3][m] = v.w;
                idx += 256;
            }
        }
        {
            int idx = tid;
#pragma unroll
            for (int it = 0; it < 4; it++) {
                int k = idx >> 5, c4 = idx & 31;
                *(float4*)&ws[k][c4 * 4] =
                    *(const float4*)&Wo[(size_t)(k0 + k) * 128 + c4 * 4];
                idx += 256;
            }
        }
        __syncthreads();
#pragma unroll
        for (int kk = 0; kk < 32; kk++) {
            float4 bv = *(const float4*)&ws[kk][tx * 4];
            u64 b0 = pack2(bv.x, bv.x), b1 = pack2(bv.y, bv.y);
            u64 b2 = pack2(bv.z, bv.z), b3 = pack2(bv.w, bv.w);
            ulonglong2 a01 = *(const ulonglong2*)&xs_t[kk][ty * 8];
            ulonglong2 a23 = *(const ulonglong2*)&xs_t[kk][ty * 8 + 4];
            acc[0][0] = ffma2(a01.x, b0, acc[0][0]);
            acc[0][1] = ffma2(a01.x, b1, acc[0][1]);
            acc[0][2] = ffma2(a01.x, b2, acc[0][2]);
            acc[0][3] = ffma2(a01.x, b3, acc[0][3]);
            acc[1][0] = ffma2(a01.y, b0, acc[1][0]);
            acc[1][1] = ffma2(a01.y, b1, acc[1][1]);
            acc[1][2] = ffma2(a01.y, b2, acc[1][2]);
            acc[1][3] = ffma2(a01.y, b3, acc[1][3]);
            acc[2][0] = ffma2(a23.x, b0, acc[2][0]);
            acc[2][1] = ffma2(a23.x, b1, acc[2][1]);
            acc[2][2] = ffma2(a23.x, b2, acc[2][2]);
            acc[2][3] = ffma2(a23.x, b3, acc[2][3]);
            acc[3][0] = ffma2(a23.y, b0, acc[3][0]);
            acc[3][1] = ffma2(a23.y, b1, acc[3][1]);
            acc[3][2] = ffma2(a23.y, b2, acc[3][2]);
            acc[3][3] = ffma2(a23.y, b3, acc[3][3]);
        }
        __syncthreads();
    }

    const int col0 = tx * 4;
#pragma unroll
    for (int p = 0; p < 4; p++) {
        float2 c0 = unpack2(acc[p][0]);
        float2 c1 = unpack2(acc[p][1]);
        float2 c2 = unpack2(acc[p][2]);
        float2 c3 = unpack2(acc[p][3]);
        float rowv[2][4] = {{c0.x, c1.x, c2.x, c3.x}, {c0.y, c1.y, c2.y, c3.y}};
#pragma unroll
        for (int rr = 0; rr < 2; rr++) {
            const int n   = m0 + ty * 8 + 2 * p + rr;
            const int t   = n / HW_;
            const int rem = n % HW_;
            const size_t o = (size_t)rem * (T_ * C_) + t * C_ + col0;
            *(float4*)&out[o] =
                make_float4(rowv[rr][0], rowv[rr][1], rowv[rr][2], rowv[rr][3]);
        }
    }
}

// ---------------------------------------------------------------------------
extern "C" void kernel_launch(void* const* d_in, const int* in_sizes, int n_in,
                              void* d_out, int out_size)
{
    const float* x    = (const float*)d_in[0];
    const float* Wq   = (const float*)d_in[1];
    const float* Wk   = (const float*)d_in[2];
    const float* Wv   = (const float*)d_in[3];
    const float* Wo   = (const float*)d_in[4];
    const float* temp = (const float*)d_in[5];
    const float* sp   = (const float*)d_in[6];
    float* out = (float*)d_out;

    qkv_kernel<<<dim3(NT / 64, 3), 256>>>(x, Wq, Wk, Wv, temp, sp);

    const size_t smem = (size_t)((120 + 120 + 12 + 25) * KPAD) * sizeof(float);
    cudaFuncSetAttribute(attn_kernel, cudaFuncAttributeMaxDynamicSharedMemorySize, (int)smem);
    attn_kernel<<<dim3(W_ / QX, H_), 768, smem>>>(sp);

    outproj_kernel<<<NT / 64, 256>>>(Wo, out);
}

// round 4
// speedup vs baseline: 1.9838x; 1.1979x over previous
#include <cuda_runtime.h>
#include <cstdint>

#define T_  3
#define H_  96
#define W_  96
#define C_  128
#define CK  128
#define NHEAD 8
#define DH  16
#define HW_ (H_*W_)
#define NT  (T_*HW_)        // 27648
#define QX  4
#define KPAD 132            // fp32 row stride
#define SLICE (24*KPAD)     // floats per y-slice (3 frames x 8 kx)
#define NSLOT 6
#define YSEG 16             // y rows per block
#define XS (W_/QX)          // 24 x-strips
#define YB (H_/YSEG)        // 6 y-segments

typedef unsigned long long u64;

__device__ float g_Q[NT*CK];
__device__ float g_K[NT*CK];
__device__ float g_V[NT*CK];
__device__ float g_O[NT*CK];

// ---------------- f32x2 helpers ----------------
__device__ __forceinline__ u64 ffma2(u64 a, u64 b, u64 c) {
    u64 d; asm("fma.rn.f32x2 %0,%1,%2,%3;" : "=l"(d) : "l"(a), "l"(b), "l"(c)); return d;
}
__device__ __forceinline__ u64 fadd2(u64 a, u64 b) {
    u64 d; asm("add.rn.f32x2 %0,%1,%2;" : "=l"(d) : "l"(a), "l"(b)); return d;
}
__device__ __forceinline__ u64 pack2(float lo, float hi) {
    u64 d; asm("mov.b64 %0,{%1,%2};" : "=l"(d) : "f"(lo), "f"(hi)); return d;
}
__device__ __forceinline__ float2 unpack2(u64 v) {
    float2 r; asm("mov.b64 {%0,%1},%2;" : "=f"(r.x), "=f"(r.y) : "l"(v)); return r;
}
__device__ __forceinline__ void cp16(uint32_t dst, const float* src) {
    asm volatile("cp.async.cg.shared.global [%0], [%1], 16;" :: "r"(dst), "l"(src));
}

__device__ __forceinline__ float fexp(float x) {
    float t = fmaxf(x * 1.4426950408889634f, -125.0f);
    float r = t + 12582912.0f;
    float f = t - (r - 12582912.0f);
    int  ri = __float_as_int(r) - 0x4B400000;
    float p =              1.5403530393e-4f;
    p = fmaf(p, f, 1.3333558146e-3f);
    p = fmaf(p, f, 9.6181291076e-3f);
    p = fmaf(p, f, 5.5504108665e-2f);
    p = fmaf(p, f, 2.4022650696e-1f);
    p = fmaf(p, f, 6.9314718056e-1f);
    p = fmaf(p, f, 1.0f);
    return p * __int_as_float((ri + 127) << 23);
}

// ---------------------------------------------------------------------------
// Kernel 1: QKV projection + embedding epilogue. f32x2 inner loop. (as R3)
// ---------------------------------------------------------------------------
__global__ __launch_bounds__(256) void qkv_kernel(
    const float* __restrict__ x,
    const float* __restrict__ Wq,
    const float* __restrict__ Wk,
    const float* __restrict__ Wv,
    const float* __restrict__ temp_emb,
    const float* __restrict__ sp_emb)
{
    __shared__ float xs_t[32][68];
    __shared__ float ws[32][128];

    const int which = blockIdx.y;
    const float* Wm = (which == 0) ? Wq : (which == 1) ? Wk : Wv;
    float* dst      = (which == 0) ? g_Q : (which == 1) ? g_K : g_V;

    const int m0  = blockIdx.x * 64;
    const int tid = threadIdx.x;
    const int tx  = tid & 31;
    const int ty  = tid >> 5;

    u64 acc[4][4];
#pragma unroll
    for (int p = 0; p < 4; p++)
#pragma unroll
        for (int j = 0; j < 4; j++) acc[p][j] = 0ull;

    for (int k0 = 0; k0 < 128; k0 += 32) {
        {
            int idx = tid;
#pragma unroll
            for (int it = 0; it < 2; it++) {
                int m = idx >> 3, k4 = idx & 7;
                float4 v = *(const float4*)&x[(size_t)(m0 + m) * 128 + k0 + k4 * 4];
                xs_t[k4 * 4 + 0][m] = v.x;
                xs_t[k4 * 4 + 1][m] = v.y;
                xs_t[k4 * 4 + 2][m] = v.z;
                xs_t[k4 * 4 + 3][m] = v.w;
                idx += 256;
            }
        }
        {
            int idx = tid;
#pragma unroll
            for (int it = 0; it < 4; it++) {
                int k = idx >> 5, c4 = idx & 31;
                *(float4*)&ws[k][c4 * 4] =
                    *(const float4*)&Wm[(size_t)(k0 + k) * 128 + c4 * 4];
                idx += 256;
            }
        }
        __syncthreads();
#pragma unroll
        for (int kk = 0; kk < 32; kk++) {
            float4 bv = *(const float4*)&ws[kk][tx * 4];
            u64 b0 = pack2(bv.x, bv.x), b1 = pack2(bv.y, bv.y);
            u64 b2 = pack2(bv.z, bv.z), b3 = pack2(bv.w, bv.w);
            ulonglong2 a01 = *(const ulonglong2*)&xs_t[kk][ty * 8];
            ulonglong2 a23 = *(const ulonglong2*)&xs_t[kk][ty * 8 + 4];
            acc[0][0] = ffma2(a01.x, b0, acc[0][0]);
            acc[0][1] = ffma2(a01.x, b1, acc[0][1]);
            acc[0][2] = ffma2(a01.x, b2, acc[0][2]);
            acc[0][3] = ffma2(a01.x, b3, acc[0][3]);
            acc[1][0] = ffma2(a01.y, b0, acc[1][0]);
            acc[1][1] = ffma2(a01.y, b1, acc[1][1]);
            acc[1][2] = ffma2(a01.y, b2, acc[1][2]);
            acc[1][3] = ffma2(a01.y, b3, acc[1][3]);
            acc[2][0] = ffma2(a23.x, b0, acc[2][0]);
            acc[2][1] = ffma2(a23.x, b1, acc[2][1]);
            acc[2][2] = ffma2(a23.x, b2, acc[2][2]);
            acc[2][3] = ffma2(a23.x, b3, acc[2][3]);
            acc[3][0] = ffma2(a23.y, b0, acc[3][0]);
            acc[3][1] = ffma2(a23.y, b1, acc[3][1]);
            acc[3][2] = ffma2(a23.y, b2, acc[3][2]);
            acc[3][3] = ffma2(a23.y, b3, acc[3][3]);
        }
        __syncthreads();
    }

    const int col0 = tx * 4;
#pragma unroll
    for (int p = 0; p < 4; p++) {
        float2 c0 = unpack2(acc[p][0]);
        float2 c1 = unpack2(acc[p][1]);
        float2 c2 = unpack2(acc[p][2]);
        float2 c3 = unpack2(acc[p][3]);
        float rowv[2][4] = {{c0.x, c1.x, c2.x, c3.x}, {c0.y, c1.y, c2.y, c3.y}};
#pragma unroll
        for (int rr = 0; rr < 2; rr++) {
            const int n   = m0 + ty * 8 + 2 * p + rr;
            const int t   = n / HW_;
            const int rem = n % HW_;
            if (which <= 1) {
#pragma unroll
                for (int j = 0; j < 4; j++) rowv[rr][j] += temp_emb[t * CK + col0 + j];
            }
            if (which == 0) {
                const int yq = rem / W_;
                const int xq = rem % W_;
                const int yc = min(max(yq, 2), H_ - 3);
                const int xc = min(max(xq, 2), W_ - 3);
                const int qidx = (yq - yc + 2) * 5 + (xq - xc + 2);
#pragma unroll
                for (int j = 0; j < 4; j++) rowv[rr][j] += sp_emb[qidx * CK + col0 + j];
            }
            *(float4*)&dst[(size_t)n * CK + col0] =
                make_float4(rowv[rr][0], rowv[rr][1], rowv[rr][2], rowv[rr][3]);
        }
    }
}

// ---------------------------------------------------------------------------
// Kernel 2: attention, rolling-window persistent blocks.
// Block = (x-strip of 4 queries, y-segment of 16). 768 thr = 24 warps (t,h).
// K/V kept in a 6-deep y-slice ring; one cp.async slice prefetch per step.
// ---------------------------------------------------------------------------
__global__ __launch_bounds__(768) void attn_kernel(const float* __restrict__ sp_emb)
{
    extern __shared__ float sm[];
    float* Kr  = sm;                        // NSLOT x 24 x KPAD
    float* Vr  = Kr + NSLOT * SLICE;
    float* SPs = Vr + NSLOT * SLICE;        // 25 x KPAD

    const uint32_t sbase = (uint32_t)__cvta_generic_to_shared(sm);
    const uint32_t Kb  = sbase;
    const uint32_t Vb  = sbase + NSLOT * SLICE * 4;
    const uint32_t SPb = Vb + NSLOT * SLICE * 4;

    const int x0  = blockIdx.x * QX;
    const int y0  = blockIdx.y * YSEG;
    const int tid = threadIdx.x;
    const int xbase = min(max(x0, 2), W_ - 3) - 2;

    // per-thread slice-load coordinates (exactly 1 float4 per thread per array)
    const int srow = tid >> 5;              // 0..23  = t*8 + kx
    const int sc4  = (tid & 31) * 4;
    const int st   = srow >> 3;
    const int scol = min(xbase + (srow & 7), W_ - 1);
    const size_t sgbase = (size_t)(st * HW_ + scol) * CK + sc4;
    const uint32_t ssoff = (srow * KPAD + sc4) * 4;

    // prologue: sp_emb + initial 5 slices
    for (int i = tid; i < 25 * 32; i += 768) {
        int p = i >> 5, c4 = (i & 31) * 4;
        cp16(SPb + (uint32_t)(p * KPAD + c4) * 4, &sp_emb[p * 128 + c4]);
    }
    const int yc0 = min(max(y0, 2), H_ - 3);
#pragma unroll
    for (int r = 0; r < 5; r++) {
        const int yr = yc0 - 2 + r;
        const uint32_t so = (uint32_t)((yr % NSLOT) * SLICE * 4) + ssoff;
        const size_t g = sgbase + (size_t)yr * W_ * CK;
        cp16(Kb + so, &g_K[g]);
        cp16(Vb + so, &g_V[g]);
    }
    asm volatile("cp.async.commit_group;");
    asm volatile("cp.async.wait_group 0;");
    __syncthreads();
    int loaded_max = yc0 + 2;

    const int lane = tid & 31;
    const int w    = tid >> 5;
    const int tq   = w / NHEAD;
    const int h    = w % NHEAD;
    const int hoff = h * DH;

    const int qx  = lane >> 3;
    const int rl  = lane & 7;
    const int xoffq = min(max(x0 + qx, 2), W_ - 3) - 2 - xbase;   // 0..3
    const int kxr   = rl - xoffq;
    const bool valid = (kxr >= 0) && (kxr <= 4);
    const int kxrc  = min(max(kxr, 0), 4);
    const int d4 = lane >> 3;

    for (int yq = y0; yq < y0 + YSEG; yq++) {
        const int yc = min(max(yq, 2), H_ - 3);

        // prefetch next slice (overlapped with compute below)
        const int need_next = min(max(yq + 1, 2), H_ - 3) + 2;
        const bool pf = (yq + 1 < y0 + YSEG) && (need_next > loaded_max);
        if (pf) {
            const uint32_t so = (uint32_t)((need_next % NSLOT) * SLICE * 4) + ssoff;
            const size_t g = sgbase + (size_t)need_next * W_ * CK;
            cp16(Kb + so, &g_K[g]);
            cp16(Vb + so, &g_V[g]);
            asm volatile("cp.async.commit_group;");
            loaded_max = need_next;
        }

        // slot indices of window rows yc-2..yc+2
        int slot[5];
        {
            int s0 = (yc - 2) % NSLOT;
#pragma unroll
            for (int i5 = 0; i5 < 5; i5++) {
                slot[i5] = s0;
                s0 = (s0 + 1 == NSLOT) ? 0 : s0 + 1;
            }
        }

        // Q direct from gmem (L2-hot)
        const float* qp = &g_Q[(size_t)(tq * HW_ + yq * W_ + x0 + qx) * CK + hoff];
        ulonglong2 qA = *(const ulonglong2*)&qp[0];
        ulonglong2 qB = *(const ulonglong2*)&qp[4];
        ulonglong2 qC = *(const ulonglong2*)&qp[8];
        ulonglong2 qD = *(const ulonglong2*)&qp[12];

        // phase 1: raw K scores
        float a[15];
#pragma unroll
        for (int tk = 0; tk < 3; tk++) {
#pragma unroll
            for (int i5 = 0; i5 < 5; i5++) {
                const float* kr = &Kr[slot[i5] * SLICE + (tk * 8 + rl) * KPAD + hoff];
                ulonglong2 k0 = *(const ulonglong2*)&kr[0];
                ulonglong2 k1 = *(const ulonglong2*)&kr[4];
                ulonglong2 k2 = *(const ulonglong2*)&kr[8];
                ulonglong2 k3 = *(const ulonglong2*)&kr[12];
                u64 s = ffma2(qA.x, k0.x, 0ull);
                s = ffma2(qA.y, k0.y, s);
                s = ffma2(qB.x, k1.x, s);
                s = ffma2(qB.y, k1.y, s);
                s = ffma2(qC.x, k2.x, s);
                s = ffma2(qC.y, k2.y, s);
                s = ffma2(qD.x, k3.x, s);
                s = ffma2(qD.y, k3.y, s);
                float2 f = unpack2(s);
                a[tk * 5 + i5] = f.x + f.y;
            }
        }

        // Q . sp_emb[p] for this lane's column
        float qsp[5];
#pragma unroll
        for (int i5 = 0; i5 < 5; i5++) {
            const float* sp = &SPs[(i5 * 5 + kxrc) * KPAD + hoff];
            ulonglong2 s0 = *(const ulonglong2*)&sp[0];
            ulonglong2 s1 = *(const ulonglong2*)&sp[4];
            ulonglong2 s2 = *(const ulonglong2*)&sp[8];
            ulonglong2 s3 = *(const ulonglong2*)&sp[12];
            u64 s = ffma2(qA.x, s0.x, 0ull);
            s = ffma2(qA.y, s0.y, s);
            s = ffma2(qB.x, s1.x, s);
            s = ffma2(qB.y, s1.y, s);
            s = ffma2(qC.x, s2.x, s);
            s = ffma2(qC.y, s2.y, s);
            s = ffma2(qD.x, s3.x, s);
            s = ffma2(qD.y, s3.y, s);
            float2 f = unpack2(s);
            qsp[i5] = f.x + f.y;
        }

        float ssum = 0.f;
#pragma unroll
        for (int tk = 0; tk < 3; tk++)
#pragma unroll
            for (int i5 = 0; i5 < 5; i5++) {
                int idx = tk * 5 + i5;
                float s = (a[idx] + qsp[i5]) * 0.25f;
                float e = valid ? fexp(s) : 0.f;
                a[idx] = e;
                ssum += e;
            }
        ssum += __shfl_xor_sync(0xffffffffu, ssum, 1);
        ssum += __shfl_xor_sync(0xffffffffu, ssum, 2);
        ssum += __shfl_xor_sync(0xffffffffu, ssum, 4);
        float rs = __fdividef(1.f, ssum);

        // phase 2: AV
        u64 acc[4][2];
#pragma unroll
        for (int q = 0; q < 4; q++) { acc[q][0] = 0ull; acc[q][1] = 0ull; }

#pragma unroll
        for (int tk = 0; tk < 3; tk++) {
#pragma unroll
            for (int i5 = 0; i5 < 5; i5++) {
                const int idx = tk * 5 + i5;
                const float* vrp = &Vr[slot[i5] * SLICE + (tk * 8 + rl) * KPAD + hoff + d4 * 4];
                ulonglong2 v = *(const ulonglong2*)vrp;
#pragma unroll
                for (int q = 0; q < 4; q++) {
                    float av = __shfl_sync(0xffffffffu, a[idx], (q << 3) | rl);
                    u64 aa = pack2(av, av);
                    acc[q][0] = ffma2(aa, v.x, acc[q][0]);
                    acc[q][1] = ffma2(aa, v.y, acc[q][1]);
                }
            }
        }
#pragma unroll
        for (int off = 1; off <= 4; off <<= 1) {
#pragma unroll
            for (int q = 0; q < 4; q++) {
                acc[q][0] = fadd2(acc[q][0], __shfl_xor_sync(0xffffffffu, acc[q][0], off));
                acc[q][1] = fadd2(acc[q][1], __shfl_xor_sync(0xffffffffu, acc[q][1], off));
            }
        }
        float rsw = __shfl_sync(0xffffffffu, rs, (lane & 7) * 8);
        if (rl < 4) {
            float2 lo = unpack2(acc[rl][0]);
            float2 hi = unpack2(acc[rl][1]);
            float4 o = make_float4(lo.x * rsw, lo.y * rsw, hi.x * rsw, hi.y * rsw);
            *(float4*)&g_O[(size_t)(tq * HW_ + yq * W_ + x0 + rl) * CK + hoff + d4 * 4] = o;
        }

        if (pf) asm volatile("cp.async.wait_group 0;");
        __syncthreads();
    }
}

// ---------------------------------------------------------------------------
// Kernel 3: output projection O @ Wo, transposed writeout. (as R3)
// ---------------------------------------------------------------------------
__global__ __launch_bounds__(256) void outproj_kernel(
    const float* __restrict__ Wo, float* __restrict__ out)
{
    __shared__ float xs_t[32][68];
    __shared__ float ws[32][128];

    const int m0  = blockIdx.x * 64;
    const int tid = threadIdx.x;
    const int tx  = tid & 31;
    const int ty  = tid >> 5;

    u64 acc[4][4];
#pragma unroll
    for (int p = 0; p < 4; p++)
#pragma unroll
        for (int j = 0; j < 4; j++) acc[p][j] = 0ull;

    for (int k0 = 0; k0 < 128; k0 += 32) {
        {
            int idx = tid;
#pragma unroll
            for (int it = 0; it < 2; it++) {
                int m = idx >> 3, k4 = idx & 7;
                float4 v = *(const float4*)&g_O[(size_t)(m0 + m) * 128 + k0 + k4 * 4];
                xs_t[k4 * 4 + 0][m] = v.x;
                xs_t[k4 * 4 + 1][m] = v.y;
                xs_t[k4 * 4 + 2][m] = v.z;
                xs_t[k4 * 4 + 3][m] = v.w;
                idx += 256;
            }
        }
        {
            int idx = tid;
#pragma unroll
            for (int it = 0; it < 4; it++) {
                int k = idx >> 5, c4 = idx & 31;
                *(float4*)&ws[k][c4 * 4] =
                    *(const float4*)&Wo[(size_t)(k0 + k) * 128 + c4 * 4];
                idx += 256;
            }
        }
        __syncthreads();
#pragma unroll
        for (int kk = 0; kk < 32; kk++) {
            float4 bv = *(const float4*)&ws[kk][tx * 4];
            u64 b0 = pack2(bv.x, bv.x), b1 = pack2(bv.y, bv.y);
            u64 b2 = pack2(bv.z, bv.z), b3 = pack2(bv.w, bv.w);
            ulonglong2 a01 = *(const ulonglong2*)&xs_t[kk][ty * 8];
            ulonglong2 a23 = *(const ulonglong2*)&xs_t[kk][ty * 8 + 4];
            acc[0][0] = ffma2(a01.x, b0, acc[0][0]);
            acc[0][1] = ffma2(a01.x, b1, acc[0][1]);
            acc[0][2] = ffma2(a01.x, b2, acc[0][2]);
            acc[0][3] = ffma2(a01.x, b3, acc[0][3]);
            acc[1][0] = ffma2(a01.y, b0, acc[1][0]);
            acc[1][1] = ffma2(a01.y, b1, acc[1][1]);
            acc[1][2] = ffma2(a01.y, b2, acc[1][2]);
            acc[1][3] = ffma2(a01.y, b3, acc[1][3]);
            acc[2][0] = ffma2(a23.x, b0, acc[2][0]);
            acc[2][1] = ffma2(a23.x, b1, acc[2][1]);
            acc[2][2] = ffma2(a23.x, b2, acc[2][2]);
            acc[2][3] = ffma2(a23.x, b3, acc[2][3]);
            acc[3][0] = ffma2(a23.y, b0, acc[3][0]);
            acc[3][1] = ffma2(a23.y, b1, acc[3][1]);
            acc[3][2] = ffma2(a23.y, b2, acc[3][2]);
            acc[3][3] = ffma2(a23.y, b3, acc[3][3]);
        }
        __syncthreads();
    }

    const int col0 = tx * 4;
#pragma unroll
    for (int p = 0; p < 4; p++) {
        float2 c0 = unpack2(acc[p][0]);
        float2 c1 = unpack2(acc[p][1]);
        float2 c2 = unpack2(acc[p][2]);
        float2 c3 = unpack2(acc[p][3]);
        float rowv[2][4] = {{c0.x, c1.x, c2.x, c3.x}, {c0.y, c1.y, c2.y, c3.y}};
#pragma unroll
        for (int rr = 0; rr < 2; rr++) {
            const int n   = m0 + ty * 8 + 2 * p + rr;
            const int t   = n / HW_;
            const int rem = n % HW_;
            const size_t o = (size_t)rem * (T_ * C_) + t * C_ + col0;
            *(float4*)&out[o] =
                make_float4(rowv[rr][0], rowv[rr][1], rowv[rr][2], rowv[rr][3]);
        }
    }
}

// ---------------------------------------------------------------------------
extern "C" void kernel_launch(void* const* d_in, const int* in_sizes, int n_in,
                              void* d_out, int out_size)
{
    const float* x    = (const float*)d_in[0];
    const float* Wq   = (const float*)d_in[1];
    const float* Wk   = (const float*)d_in[2];
    const float* Wv   = (const float*)d_in[3];
    const float* Wo   = (const float*)d_in[4];
    const float* temp = (const float*)d_in[5];
    const float* sp   = (const float*)d_in[6];
    float* out = (float*)d_out;

    qkv_kernel<<<dim3(NT / 64, 3), 256>>>(x, Wq, Wk, Wv, temp, sp);

    const size_t smem = (size_t)(2 * NSLOT * SLICE + 25 * KPAD) * sizeof(float);
    cudaFuncSetAttribute(attn_kernel, cudaFuncAttributeMaxDynamicSharedMemorySize, (int)smem);
    attn_kernel<<<dim3(XS, YB), 768, smem>>>(sp);

    outproj_kernel<<<NT / 64, 256>>>(Wo, out);
}